// round 8
// baseline (speedup 1.0000x reference)
#include <cuda_runtime.h>

// Problem constants (fixed by setup_inputs)
#define H 512
#define T_TREES 1024
#define N0 65536

// ---------------- device scratch (no allocs allowed) ----------------
__device__ float g_S[T_TREES * H];     // pooled leaf sums  [1024, 512]
__device__ float g_WsT[H * H];         // Wsum^T
__device__ float g_WzfT[H * H];        // Wzf^T
__device__ float g_N[H * H];           // N  = M^T
__device__ float g_N2[H * H];          // N^2
__device__ float g_SN[T_TREES * H];    // S @ N
__device__ float g_c[H];
__device__ float g_d[H];
__device__ float g_part[8 * H * H];          // split-K partials (chain gemms, K<=8)
__device__ float g_partF[4 * T_TREES * H];   // split-K partials (1024-row gemms, K<=4)

// ---------------- pooling: S[t] = sum of 64 consecutive x rows ----------------
__global__ __launch_bounds__(256) void k_pool(const float4* __restrict__ x4) {
    int tid = threadIdx.x;
    int t = blockIdx.x * 2 + (tid >> 7);   // 512 blocks -> 1024 trees
    int q = tid & 127;                     // float4 column (H/4 = 128)
    const float4* p = x4 + (size_t)t * 64 * 128 + q;
    float4 s = make_float4(0.f, 0.f, 0.f, 0.f);
#pragma unroll 16
    for (int r = 0; r < 64; ++r) {
        float4 v = p[(size_t)r * 128];
        s.x += v.x; s.y += v.y; s.z += v.z; s.w += v.w;
    }
    reinterpret_cast<float4*>(g_S)[t * 128 + q] = s;
}

// ---------------- prep: Wsum^T, Wzf^T (tiled transpose) ----------------
__global__ __launch_bounds__(256) void k_prep(const float* __restrict__ Wz,
                                              const float* __restrict__ Wzf) {
    __shared__ float tile[32][33];
    int b = blockIdx.x;
    int tx = threadIdx.x & 31, ty = threadIdx.x >> 5;  // 32 x 8
    if (b < 256) {
        int bx = b & 15, by = b >> 4;
#pragma unroll
        for (int i = 0; i < 4; ++i) {
            int r = by * 32 + ty + i * 8;
            int c = bx * 32 + tx;
            float v = Wz[0 * H * H + r * H + c] + Wz[1 * H * H + r * H + c]
                    + Wz[2 * H * H + r * H + c] + Wz[3 * H * H + r * H + c];
            tile[ty + i * 8][tx] = v;
        }
        __syncthreads();
#pragma unroll
        for (int i = 0; i < 4; ++i)
            g_WsT[(bx * 32 + ty + i * 8) * H + by * 32 + tx] = tile[tx][ty + i * 8];
    } else {
        int bb = b - 256;
        int bx = bb & 15, by = bb >> 4;
#pragma unroll
        for (int i = 0; i < 4; ++i)
            tile[ty + i * 8][tx] = Wzf[(by * 32 + ty + i * 8) * H + bx * 32 + tx];
        __syncthreads();
#pragma unroll
        for (int i = 0; i < 4; ++i)
            g_WzfT[(bx * 32 + ty + i * 8) * H + by * 32 + tx] = tile[tx][ty + i * 8];
    }
}

// ---------------- c = 4 * (Wzf @ bsum + bzf), self-contained ----------------
__global__ __launch_bounds__(256) void k_c(const float* __restrict__ bz,
                                           const float* __restrict__ Wzf,
                                           const float* __restrict__ bzf) {
    __shared__ float sb[H];
    int tid = threadIdx.x;
#pragma unroll
    for (int i = 0; i < 2; ++i) {
        int hh = tid + i * 256;
        sb[hh] = bz[hh] + bz[H + hh] + bz[2 * H + hh] + bz[3 * H + hh];
    }
    __syncthreads();
    int j = blockIdx.x * 256 + tid;
    float acc = 0.f;
#pragma unroll 8
    for (int h = 0; h < H; ++h)
        acc += Wzf[(size_t)j * H + h] * sb[h];
    g_c[j] = 4.0f * (acc + bzf[j]);
}

// ---------------- d = 16 M^2 c + 4 M c + c  (via N = M^T) ----------------
__global__ __launch_bounds__(256) void k_d() {
    int j = blockIdx.x * 256 + threadIdx.x;
    float acc = 0.f;
#pragma unroll 8
    for (int h = 0; h < H; ++h) {
        float ch = g_c[h];
        acc += ch * (16.0f * g_N2[h * H + j] + 4.0f * g_N[h * H + j]);
    }
    g_d[j] = acc + g_c[j];
}

// ---------------- NN GEMM, 128x128 tile, 8x8 microtile, split-K ----------------
// C_partial[z] = A[M x 512] @ B[512 x 512] over k-slice z.
// grid = (M/128, 4, SPLITK), block = 256. BK=16, double-buffered SMEM,
// register prefetch. 64 FMA per 4 LDS.128 in the inner loop.
__global__ __launch_bounds__(256) void k_gemm(const float* __restrict__ A,
                                              const float* __restrict__ B,
                                              float* __restrict__ Cp) {
    __shared__ float As[2][16][128];
    __shared__ float Bs[2][16][128];
    const int tid = threadIdx.x;
    const int tx = tid & 15, ty = tid >> 4;
    const int rb = blockIdx.x * 128, cb = blockIdx.y * 128;
    const int Mrows = gridDim.x * 128;
    const int kslice = H / gridDim.z;
    const int k0base = blockIdx.z * kslice;
    const int nk = kslice / 16;

    // A loader: row lar = tid>>1, k-offset lak = (tid&1)*8 (two float4 each)
    const int lar = tid >> 1;
    const int lak = (tid & 1) * 8;
    // B loader: k-row lbk = tid>>4, col quads tx*4 and 64+tx*4
    const int lbk = tid >> 4;
    const int lbc = tx * 4;

    const float* Arow = &A[(size_t)(rb + lar) * H + k0base + lak];
    const float* Brow = &B[(size_t)(k0base + lbk) * H + cb];

    float4 ra0 = *reinterpret_cast<const float4*>(Arow);
    float4 ra1 = *reinterpret_cast<const float4*>(Arow + 4);
    float4 rb0 = *reinterpret_cast<const float4*>(Brow + lbc);
    float4 rb1 = *reinterpret_cast<const float4*>(Brow + 64 + lbc);

    As[0][lak + 0][lar] = ra0.x; As[0][lak + 1][lar] = ra0.y;
    As[0][lak + 2][lar] = ra0.z; As[0][lak + 3][lar] = ra0.w;
    As[0][lak + 4][lar] = ra1.x; As[0][lak + 5][lar] = ra1.y;
    As[0][lak + 6][lar] = ra1.z; As[0][lak + 7][lar] = ra1.w;
    *reinterpret_cast<float4*>(&Bs[0][lbk][lbc])      = rb0;
    *reinterpret_cast<float4*>(&Bs[0][lbk][64 + lbc]) = rb1;
    __syncthreads();

    float acc[8][8];
#pragma unroll
    for (int i = 0; i < 8; ++i)
#pragma unroll
        for (int j = 0; j < 8; ++j) acc[i][j] = 0.f;

    for (int kt = 0; kt < nk; ++kt) {
        int cur = kt & 1, nxt = cur ^ 1;
        if (kt + 1 < nk) {
            int koff = (kt + 1) * 16;
            ra0 = *reinterpret_cast<const float4*>(Arow + koff);
            ra1 = *reinterpret_cast<const float4*>(Arow + koff + 4);
            rb0 = *reinterpret_cast<const float4*>(Brow + (size_t)koff * H + lbc);
            rb1 = *reinterpret_cast<const float4*>(Brow + (size_t)koff * H + 64 + lbc);
        }
#pragma unroll
        for (int kk = 0; kk < 16; ++kk) {
            float4 a0 = *reinterpret_cast<const float4*>(&As[cur][kk][ty * 4]);
            float4 a1 = *reinterpret_cast<const float4*>(&As[cur][kk][64 + ty * 4]);
            float4 b0 = *reinterpret_cast<const float4*>(&Bs[cur][kk][tx * 4]);
            float4 b1 = *reinterpret_cast<const float4*>(&Bs[cur][kk][64 + tx * 4]);
            float aa[8] = {a0.x, a0.y, a0.z, a0.w, a1.x, a1.y, a1.z, a1.w};
            float bb[8] = {b0.x, b0.y, b0.z, b0.w, b1.x, b1.y, b1.z, b1.w};
#pragma unroll
            for (int i = 0; i < 8; ++i)
#pragma unroll
                for (int j = 0; j < 8; ++j)
                    acc[i][j] += aa[i] * bb[j];
        }
        if (kt + 1 < nk) {
            As[nxt][lak + 0][lar] = ra0.x; As[nxt][lak + 1][lar] = ra0.y;
            As[nxt][lak + 2][lar] = ra0.z; As[nxt][lak + 3][lar] = ra0.w;
            As[nxt][lak + 4][lar] = ra1.x; As[nxt][lak + 5][lar] = ra1.y;
            As[nxt][lak + 6][lar] = ra1.z; As[nxt][lak + 7][lar] = ra1.w;
            *reinterpret_cast<float4*>(&Bs[nxt][lbk][lbc])      = rb0;
            *reinterpret_cast<float4*>(&Bs[nxt][lbk][64 + lbc]) = rb1;
        }
        __syncthreads();
    }

    float* C = Cp + (size_t)blockIdx.z * Mrows * H;
#pragma unroll
    for (int ih = 0; ih < 8; ++ih) {
        int row = rb + (ih >> 2) * 64 + ty * 4 + (ih & 3);
        *reinterpret_cast<float4*>(&C[(size_t)row * H + cb + tx * 4]) =
            make_float4(acc[ih][0], acc[ih][1], acc[ih][2], acc[ih][3]);
        *reinterpret_cast<float4*>(&C[(size_t)row * H + cb + 64 + tx * 4]) =
            make_float4(acc[ih][4], acc[ih][5], acc[ih][6], acc[ih][7]);
    }
}

// ---------------- combine 8 split-K partials (chain gemms, 512x512) ----------------
__global__ __launch_bounds__(256) void k_combine8(float* __restrict__ dst) {
    int i = blockIdx.x * 256 + threadIdx.x;     // float4 index; grid 256 -> 65536
    const float4* p = reinterpret_cast<const float4*>(g_part);
    float4 r = make_float4(0.f, 0.f, 0.f, 0.f);
#pragma unroll
    for (int s = 0; s < 8; ++s) {
        float4 v = p[i + s * 65536];
        r.x += v.x; r.y += v.y; r.z += v.z; r.w += v.w;
    }
    reinterpret_cast<float4*>(dst)[i] = r;
}

// ---------------- combine 4 split-K partials (SN, 1024x512) ----------------
__global__ __launch_bounds__(256) void k_combineSN() {
    int i = blockIdx.x * 256 + threadIdx.x;     // float4 index; grid 512 -> 131072
    const float4* p = reinterpret_cast<const float4*>(g_partF);
    float4 r = make_float4(0.f, 0.f, 0.f, 0.f);
#pragma unroll
    for (int s = 0; s < 4; ++s) {
        float4 v = p[i + s * 131072];
        r.x += v.x; r.y += v.y; r.z += v.z; r.w += v.w;
    }
    reinterpret_cast<float4*>(g_SN)[i] = r;
}

// ---------------- combine 4 split-K partials + bias d (final) ----------------
__global__ __launch_bounds__(256) void k_combineF(float* __restrict__ out) {
    int i = blockIdx.x * 256 + threadIdx.x;     // float4 index; grid 512 -> 131072
    const float4* p = reinterpret_cast<const float4*>(g_partF);
    float4 r = make_float4(0.f, 0.f, 0.f, 0.f);
#pragma unroll
    for (int s = 0; s < 4; ++s) {
        float4 v = p[i + s * 131072];
        r.x += v.x; r.y += v.y; r.z += v.z; r.w += v.w;
    }
    float4 dv = reinterpret_cast<const float4*>(g_d)[i & 127];
    r.x += dv.x; r.y += dv.y; r.z += dv.z; r.w += dv.w;
    reinterpret_cast<float4*>(out)[i] = r;
}

// ---------------- launch (multi-stream graph: fork/join via events) ----------------
extern "C" void kernel_launch(void* const* d_in, const int* in_sizes, int n_in,
                              void* d_out, int out_size) {
    const float* x   = (const float*)d_in[0];
    const float* Wz  = (const float*)d_in[1];
    const float* bz  = (const float*)d_in[2];
    const float* Wzf = (const float*)d_in[3];
    const float* bzf = (const float*)d_in[4];
    float* out = (float*)d_out;

    float *pS, *pWsT, *pWzfT, *pN, *pN2, *pSN, *pPart, *pPartF;
    cudaGetSymbolAddress((void**)&pS,     g_S);
    cudaGetSymbolAddress((void**)&pWsT,   g_WsT);
    cudaGetSymbolAddress((void**)&pWzfT,  g_WzfT);
    cudaGetSymbolAddress((void**)&pN,     g_N);
    cudaGetSymbolAddress((void**)&pN2,    g_N2);
    cudaGetSymbolAddress((void**)&pSN,    g_SN);
    cudaGetSymbolAddress((void**)&pPart,  g_part);
    cudaGetSymbolAddress((void**)&pPartF, g_partF);

    // Lazy one-time stream/event creation (host-side only; no device memory).
    static cudaStream_t sB = nullptr, sC = nullptr;
    static cudaEvent_t evFork = nullptr, evPool = nullptr, evN = nullptr,
                       evSN = nullptr;
    if (sB == nullptr) {
        cudaStreamCreateWithFlags(&sB, cudaStreamNonBlocking);
        cudaStreamCreateWithFlags(&sC, cudaStreamNonBlocking);
        cudaEventCreateWithFlags(&evFork, cudaEventDisableTiming);
        cudaEventCreateWithFlags(&evPool, cudaEventDisableTiming);
        cudaEventCreateWithFlags(&evN,    cudaEventDisableTiming);
        cudaEventCreateWithFlags(&evSN,   cudaEventDisableTiming);
    }

    // ---- fork side streams off the capture (legacy) stream ----
    cudaEventRecord(evFork, 0);
    cudaStreamWaitEvent(sB, evFork, 0);
    cudaStreamWaitEvent(sC, evFork, 0);

    // stream B: pooled leaf sums (DRAM-bound), overlapped with weight chain
    k_pool<<<512, 256, 0, sB>>>((const float4*)x);
    cudaEventRecord(evPool, sB);

    // stream C: c = 4 (Wzf bsum + bzf) — self-contained, off critical path
    k_c<<<2, 256, 0, sC>>>(bz, Wzf, bzf);

    // stream 0 (critical path): prep -> N = Wsum^T @ Wzf^T
    k_prep<<<512, 256>>>(Wz, Wzf);
    k_gemm<<<dim3(4, 4, 8), 256>>>(pWsT, pWzfT, pPart);
    k_combine8<<<256, 256>>>(pN);
    cudaEventRecord(evN, 0);

    // stream C: SN = S @ N (needs pool + N), overlapped with N^2
    cudaStreamWaitEvent(sC, evPool, 0);
    cudaStreamWaitEvent(sC, evN, 0);
    k_gemm<<<dim3(8, 4, 4), 256, 0, sC>>>(pS, pN, pPartF);
    k_combineSN<<<512, 256, 0, sC>>>();
    cudaEventRecord(evSN, sC);

    // stream 0: N2 = N @ N
    k_gemm<<<dim3(4, 4, 8), 256>>>(pN, pN, pPart);
    k_combine8<<<256, 256>>>(pN2);

    // stream 0: out = SN @ N2 + d
    cudaStreamWaitEvent(0, evSN, 0);
    k_gemm<<<dim3(8, 4, 4), 256>>>(pSN, pN2, pPartF);
    k_d<<<2, 256>>>();   // needs N, N2, c — all ready; feeds only combineF
    k_combineF<<<512, 256>>>(out);
}